// round 1
// baseline (speedup 1.0000x reference)
#include <cuda_runtime.h>
#include <cuda_bf16.h>

// Lp_Conv2D_BT: out[b,o,i,j] = max_{k<4} | w[o,k] - x_pad[b, c_k, i+di_k, j+dj_k] | + bias[o]
// pad = edge padding of 1 on each side (PADDING=2, pad_l=pad_r=1), stride 1.
// x: (32,64,64,64) f32; weights: (128,4) f32; bias: (128,1,1) f32; conn_idx: (128,4) i32.
// Output: (32,128,64,64) f32.

namespace {
constexpr int HW   = 64;
constexpr int CIN  = 64;
constexpr int COUT = 128;
constexpr int CONN = 4;
}

__global__ __launch_bounds__(256) void lp_conv_bt_kernel(
    const float* __restrict__ x,
    const float* __restrict__ weights,
    const float* __restrict__ bias,
    const int*   __restrict__ conn_idx,
    float*       __restrict__ out)
{
    const int blk = blockIdx.x;          // blk = b*COUT + o
    const int o   = blk & (COUT - 1);
    const int b   = blk >> 7;            // COUT = 128
    const int t   = threadIdx.x;

    // Per-output-channel connection parameters (uniform across the block).
    const float* px[CONN];
    int dr[CONN], dc[CONN];
    float w[CONN];
#pragma unroll
    for (int k = 0; k < CONN; ++k) {
        const int idx = __ldg(conn_idx + o * CONN + k);   // in [0, 576)
        const int c   = idx / 9;
        const int rem = idx - c * 9;
        const int di  = rem / 3;
        dr[k] = di - 1;                   // row offset after removing pad_l=1
        dc[k] = (rem - di * 3) - 1;       // col offset in {-1, 0, +1}
        px[k] = x + ((size_t)b * CIN + c) * (HW * HW);
        w[k]  = __ldg(weights + o * CONN + k);
    }
    const float bs = __ldg(bias + o);

    float4* po = reinterpret_cast<float4*>(out + (size_t)blk * (HW * HW));

    // Thread -> 4 consecutive columns, 4 row-blocks of 16 rows.
    const int lane16 = t & 15;
    const int j4     = lane16 << 2;      // 0..60, 16-byte aligned column group
    const int i0     = t >> 4;           // 0..15

#pragma unroll
    for (int ib = 0; ib < 4; ++ib) {
        const int i = i0 + ib * 16;
        float m0 = 0.f, m1 = 0.f, m2 = 0.f, m3 = 0.f;  // |.| >= 0, so 0-init is exact

#pragma unroll
        for (int k = 0; k < CONN; ++k) {
            int rr = i + dr[k];
            rr = min(max(rr, 0), HW - 1);               // edge-padding row clamp
            const float* prow = px[k] + rr * HW;

            // One aligned float4 covering cols [j4, j4+3], plus at most one edge
            // scalar to realize the dc in {-1,0,+1} shift. dc is block-uniform ->
            // no divergence.
            const float4 v = __ldg(reinterpret_cast<const float4*>(prow + j4));
            float g0, g1, g2, g3;
            if (dc[k] == 0) {
                g0 = v.x; g1 = v.y; g2 = v.z; g3 = v.w;
            } else if (dc[k] > 0) {                      // need cols j4+1 .. j4+4
                const float e = __ldg(prow + min(j4 + 4, HW - 1));
                g0 = v.y; g1 = v.z; g2 = v.w; g3 = e;
            } else {                                     // need cols j4-1 .. j4+2
                const float e = __ldg(prow + max(j4 - 1, 0));
                g0 = e; g1 = v.x; g2 = v.y; g3 = v.z;
            }

            const float wk = w[k];
            m0 = fmaxf(m0, fabsf(wk - g0));
            m1 = fmaxf(m1, fabsf(wk - g1));
            m2 = fmaxf(m2, fabsf(wk - g2));
            m3 = fmaxf(m3, fabsf(wk - g3));
        }

        po[i * 16 + lane16] = make_float4(m0 + bs, m1 + bs, m2 + bs, m3 + bs);
    }
}

extern "C" void kernel_launch(void* const* d_in, const int* in_sizes, int n_in,
                              void* d_out, int out_size) {
    const float* x       = (const float*)d_in[0];
    const float* weights = (const float*)d_in[1];
    const float* bias    = (const float*)d_in[2];
    const int*   conn    = (const int*)d_in[3];
    float*       out     = (float*)d_out;

    const int B = in_sizes[0] / (CIN * HW * HW);   // 32
    lp_conv_bt_kernel<<<B * COUT, 256>>>(x, weights, bias, conn, out);
}

// round 2
// speedup vs baseline: 1.1298x; 1.1298x over previous
#include <cuda_runtime.h>
#include <cuda_bf16.h>

// Lp_Conv2D_BT: out[b,o,i,j] = max_{k<4} | w[o,k] - x_pad[b, c_k, i+di_k-1, j+dj_k-1] | + bias[o]
// edge padding (clamp), stride 1.
// x:(32,64,64,64) f32; weights:(128,4) f32; bias:(128,1,1) f32; conn_idx:(128,4) i32.
// out:(32,128,64,64) f32.

namespace {
constexpr int HW   = 64;
constexpr int CIN  = 64;
constexpr int COUT = 128;
constexpr int CONN = 4;
}

__global__ __launch_bounds__(256) void lp_conv_bt_kernel(
    const float* __restrict__ x,
    const float* __restrict__ weights,
    const float* __restrict__ bias,
    const int*   __restrict__ conn_idx,
    float*       __restrict__ out)
{
    const int blk = blockIdx.x;          // blk = b*COUT + o
    const int o   = blk & (COUT - 1);
    const int b   = blk >> 7;
    const int t   = threadIdx.x;

    // Per-output-channel connection parameters (uniform across the block).
    const float* px[CONN];
    int dr[CONN], dc[CONN];
    float w[CONN];
#pragma unroll
    for (int k = 0; k < CONN; ++k) {
        const int idx = __ldg(conn_idx + o * CONN + k);   // [0, 576)
        const int c   = idx / 9;
        const int rem = idx - c * 9;
        const int di  = rem / 3;
        dr[k] = di - 1;
        dc[k] = (rem - di * 3) - 1;       // {-1, 0, +1}, uniform per block
        px[k] = x + ((size_t)b * CIN + c) * (HW * HW);
        w[k]  = __ldg(weights + o * CONN + k);
    }
    const float bs = __ldg(bias + o);

    // 8 lanes cover one row (8 cols each); thread handles rows r0 and r0+32.
    const int lane8 = t & 7;
    const int r0    = t >> 3;            // 0..31
    float4* po = reinterpret_cast<float4*>(out + (size_t)blk * (HW * HW));

#pragma unroll
    for (int rb = 0; rb < 2; ++rb) {
        const int row = r0 + rb * 32;
        float m0 = 0.f, m1 = 0.f, m2 = 0.f, m3 = 0.f;
        float m4 = 0.f, m5 = 0.f, m6 = 0.f, m7 = 0.f;   // |.| >= 0

#pragma unroll
        for (int k = 0; k < CONN; ++k) {
            int rr = row + dr[k];
            rr = min(max(rr, 0), HW - 1);
            const float4* p = reinterpret_cast<const float4*>(px[k] + rr * HW);

            const float4 v0 = __ldg(p + lane8 * 2);      // cols c0..c0+3
            const float4 v1 = __ldg(p + lane8 * 2 + 1);  // cols c0+4..c0+7

            float g0, g1, g2, g3, g4, g5, g6, g7;
            if (dc[k] == 0) {
                g0 = v0.x; g1 = v0.y; g2 = v0.z; g3 = v0.w;
                g4 = v1.x; g5 = v1.y; g6 = v1.z; g7 = v1.w;
            } else if (dc[k] > 0) {
                // input cols c0+1..c0+8 ; c0+8 = next lane's v0.x (col 64 -> clamp 63 = v1.w)
                float e = __shfl_sync(0xffffffffu, v0.x, lane8 + 1, 8);
                if (lane8 == 7) e = v1.w;
                g0 = v0.y; g1 = v0.z; g2 = v0.w; g3 = v1.x;
                g4 = v1.y; g5 = v1.z; g6 = v1.w; g7 = e;
            } else {
                // input cols c0-1..c0+6 ; c0-1 = prev lane's v1.w (col -1 -> clamp 0 = v0.x)
                float e = __shfl_sync(0xffffffffu, v1.w, lane8 - 1, 8);
                if (lane8 == 0) e = v0.x;
                g0 = e;    g1 = v0.x; g2 = v0.y; g3 = v0.z;
                g4 = v0.w; g5 = v1.x; g6 = v1.y; g7 = v1.z;
            }

            const float wk = w[k];
            m0 = fmaxf(m0, fabsf(wk - g0));
            m1 = fmaxf(m1, fabsf(wk - g1));
            m2 = fmaxf(m2, fabsf(wk - g2));
            m3 = fmaxf(m3, fabsf(wk - g3));
            m4 = fmaxf(m4, fabsf(wk - g4));
            m5 = fmaxf(m5, fabsf(wk - g5));
            m6 = fmaxf(m6, fabsf(wk - g6));
            m7 = fmaxf(m7, fabsf(wk - g7));
        }

        po[row * 16 + lane8 * 2]     = make_float4(m0 + bs, m1 + bs, m2 + bs, m3 + bs);
        po[row * 16 + lane8 * 2 + 1] = make_float4(m4 + bs, m5 + bs, m6 + bs, m7 + bs);
    }
}

extern "C" void kernel_launch(void* const* d_in, const int* in_sizes, int n_in,
                              void* d_out, int out_size) {
    const float* x       = (const float*)d_in[0];
    const float* weights = (const float*)d_in[1];
    const float* bias    = (const float*)d_in[2];
    const int*   conn    = (const int*)d_in[3];
    float*       out     = (float*)d_out;

    const int B = in_sizes[0] / (CIN * HW * HW);   // 32
    lp_conv_bt_kernel<<<B * COUT, 256>>>(x, weights, bias, conn, out);
}

// round 3
// speedup vs baseline: 1.2605x; 1.1157x over previous
#include <cuda_runtime.h>
#include <cuda_bf16.h>

// Lp_Conv2D_BT: out[b,o,i,j] = max_{k<4} | w[o,k] - x_pad[b, c_k, i+di_k-1, j+dj_k-1] | + bias[o]
// edge padding (clamp), stride 1.
// x:(32,64,64,64) f32; weights:(128,4) f32; bias:(128,1,1) f32; conn_idx:(128,4) i32.
// out:(32,128,64,64) f32.

namespace {
constexpr int HW   = 64;
constexpr int CIN  = 64;
constexpr int COUT = 128;
constexpr int CONN = 4;
}

__global__ __launch_bounds__(256) void lp_conv_bt_kernel(
    const float* __restrict__ x,
    const float* __restrict__ weights,
    const float* __restrict__ bias,
    const int*   __restrict__ conn_idx,
    float*       __restrict__ out)
{
    const int blk = blockIdx.x;          // blk = b*COUT + o
    const int o   = blk & (COUT - 1);
    const int b   = blk >> 7;
    const int t   = threadIdx.x;

    // Per-output-channel connection parameters (uniform across the block).
    const float* px[CONN];
    int dr[CONN], dc[CONN];
    float w[CONN];
#pragma unroll
    for (int k = 0; k < CONN; ++k) {
        const int idx = __ldg(conn_idx + o * CONN + k);   // [0, 576)
        const int c   = idx / 9;
        const int rem = idx - c * 9;
        const int di  = rem / 3;
        dr[k] = di - 1;
        dc[k] = (rem - di * 3) - 1;       // {-1, 0, +1}, uniform per block
        px[k] = x + ((size_t)b * CIN + c) * (HW * HW);
        w[k]  = __ldg(weights + o * CONN + k);
    }
    const float bs = __ldg(bias + o);

    // 8 lanes cover one row (8 cols each); thread handles rows r0 and r0+32.
    const int lane8 = t & 7;
    const int r0    = t >> 3;            // 0..31
    float4* po = reinterpret_cast<float4*>(out + (size_t)blk * (HW * HW));

#pragma unroll
    for (int rb = 0; rb < 2; ++rb) {
        const int row = r0 + rb * 32;
        float m0 = 0.f, m1 = 0.f, m2 = 0.f, m3 = 0.f;
        float m4 = 0.f, m5 = 0.f, m6 = 0.f, m7 = 0.f;   // |.| >= 0

        // Process k in pairs: issue 4 independent LDG.128 before any dependent op.
#pragma unroll
        for (int kp = 0; kp < CONN; kp += 2) {
            const float4* p0;
            const float4* p1;
            {
                int ra = row + dr[kp];
                int rbn = row + dr[kp + 1];
                if (rb == 0) {            // rows 0..31: only lower clamp possible
                    ra  = max(ra, 0);
                    rbn = max(rbn, 0);
                } else {                  // rows 32..63: only upper clamp possible
                    ra  = min(ra, HW - 1);
                    rbn = min(rbn, HW - 1);
                }
                p0 = reinterpret_cast<const float4*>(px[kp]     + ra  * HW) + lane8 * 2;
                p1 = reinterpret_cast<const float4*>(px[kp + 1] + rbn * HW) + lane8 * 2;
            }
            const float4 a0 = __ldg(p0);
            const float4 a1 = __ldg(p0 + 1);
            const float4 b0 = __ldg(p1);
            const float4 b1 = __ldg(p1 + 1);

#pragma unroll
            for (int kk = 0; kk < 2; ++kk) {
                const int   k  = kp + kk;
                const float4 v0 = kk ? b0 : a0;
                const float4 v1 = kk ? b1 : a1;

                float g0, g1, g2, g3, g4, g5, g6, g7;
                if (dc[k] == 0) {
                    g0 = v0.x; g1 = v0.y; g2 = v0.z; g3 = v0.w;
                    g4 = v1.x; g5 = v1.y; g6 = v1.z; g7 = v1.w;
                } else if (dc[k] > 0) {
                    // cols j0+1..j0+8 ; j0+8 = next lane's v0.x (col 64 -> clamp 63 = v1.w)
                    float e = __shfl_sync(0xffffffffu, v0.x, lane8 + 1, 8);
                    if (lane8 == 7) e = v1.w;
                    g0 = v0.y; g1 = v0.z; g2 = v0.w; g3 = v1.x;
                    g4 = v1.y; g5 = v1.z; g6 = v1.w; g7 = e;
                } else {
                    // cols j0-1..j0+6 ; j0-1 = prev lane's v1.w (col -1 -> clamp 0 = v0.x)
                    float e = __shfl_sync(0xffffffffu, v1.w, lane8 - 1, 8);
                    if (lane8 == 0) e = v0.x;
                    g0 = e;    g1 = v0.x; g2 = v0.y; g3 = v0.z;
                    g4 = v0.w; g5 = v1.x; g6 = v1.y; g7 = v1.z;
                }

                const float wk = w[k];
                m0 = fmaxf(m0, fabsf(wk - g0));
                m1 = fmaxf(m1, fabsf(wk - g1));
                m2 = fmaxf(m2, fabsf(wk - g2));
                m3 = fmaxf(m3, fabsf(wk - g3));
                m4 = fmaxf(m4, fabsf(wk - g4));
                m5 = fmaxf(m5, fabsf(wk - g5));
                m6 = fmaxf(m6, fabsf(wk - g6));
                m7 = fmaxf(m7, fabsf(wk - g7));
            }
        }

        // Streaming stores: output is never re-read; keep L2 for the x gathers.
        __stcs(po + row * 16 + lane8 * 2,
               make_float4(m0 + bs, m1 + bs, m2 + bs, m3 + bs));
        __stcs(po + row * 16 + lane8 * 2 + 1,
               make_float4(m4 + bs, m5 + bs, m6 + bs, m7 + bs));
    }
}

extern "C" void kernel_launch(void* const* d_in, const int* in_sizes, int n_in,
                              void* d_out, int out_size) {
    const float* x       = (const float*)d_in[0];
    const float* weights = (const float*)d_in[1];
    const float* bias    = (const float*)d_in[2];
    const int*   conn    = (const int*)d_in[3];
    float*       out     = (float*)d_out;

    const int B = in_sizes[0] / (CIN * HW * HW);   // 32
    lp_conv_bt_kernel<<<B * COUT, 256>>>(x, weights, bias, conn, out);
}

// round 4
// speedup vs baseline: 1.2927x; 1.0255x over previous
#include <cuda_runtime.h>
#include <cuda_bf16.h>

// Lp_Conv2D_BT: out[b,o,i,j] = max_{k<4} | w[o,k] - x_pad[b, c_k, i+di_k-1, j+dj_k-1] | + bias[o]
// edge padding (clamp), stride 1.
// x:(32,64,64,64) f32; weights:(128,4) f32; bias:(128,1,1) f32; conn_idx:(128,4) i32.
// out:(32,128,64,64) f32.

namespace {
constexpr int HW   = 64;
constexpr int CIN  = 64;
constexpr int COUT = 128;
constexpr int CONN = 4;
}

__global__ __launch_bounds__(128) void lp_conv_bt_kernel(
    const float* __restrict__ x,
    const float* __restrict__ weights,
    const float* __restrict__ bias,
    const int*   __restrict__ conn_idx,
    float*       __restrict__ out)
{
    const int blk = blockIdx.x;          // blk = b*COUT + o
    const int o   = blk & (COUT - 1);
    const int b   = blk >> 7;
    const int t   = threadIdx.x;

    // Per-output-channel connection parameters (uniform across the block).
    const float* px[CONN];
    int dr[CONN], dc[CONN];
    float w[CONN];
#pragma unroll
    for (int k = 0; k < CONN; ++k) {
        const int idx = __ldg(conn_idx + o * CONN + k);   // [0, 576)
        const int c   = idx / 9;
        const int rem = idx - c * 9;
        const int di  = rem / 3;
        dr[k] = di - 1;                   // {-1,0,1}
        dc[k] = (rem - di * 3) - 1;       // {-1,0,1}, uniform per block
        px[k] = x + ((size_t)b * CIN + c) * (HW * HW);
        w[k]  = __ldg(weights + o * CONN + k);
    }
    const float bs = __ldg(bias + o);

    // 8 lanes cover one row (8 cols each); thread handles rows r0 + {0,16,32,48}.
    const int lane8 = t & 7;
    const int r0    = t >> 3;            // 0..15
    float4* po = reinterpret_cast<float4*>(out + (size_t)blk * (HW * HW));

#pragma unroll
    for (int rb = 0; rb < 4; ++rb) {
        const int row = r0 + rb * 16;

        // Row clamp only ever needed at the extreme row-blocks (dr in {-1,0,1}).
        const float4* p[CONN];
#pragma unroll
        for (int k = 0; k < CONN; ++k) {
            int rr = row + dr[k];
            if (rb == 0)      rr = max(rr, 0);
            else if (rb == 3) rr = min(rr, HW - 1);
            p[k] = reinterpret_cast<const float4*>(px[k] + rr * HW) + lane8 * 2;
        }

        // Issue all 8 independent LDG.128 before any dependent op (MLP=8).
        float4 v[2 * CONN];
#pragma unroll
        for (int k = 0; k < CONN; ++k) {
            v[2 * k]     = __ldg(p[k]);
            v[2 * k + 1] = __ldg(p[k] + 1);
        }

        float m0 = 0.f, m1 = 0.f, m2 = 0.f, m3 = 0.f;
        float m4 = 0.f, m5 = 0.f, m6 = 0.f, m7 = 0.f;   // |.| >= 0

#pragma unroll
        for (int k = 0; k < CONN; ++k) {
            const float4 v0 = v[2 * k];
            const float4 v1 = v[2 * k + 1];

            float g0, g1, g2, g3, g4, g5, g6, g7;
            if (dc[k] == 0) {
                g0 = v0.x; g1 = v0.y; g2 = v0.z; g3 = v0.w;
                g4 = v1.x; g5 = v1.y; g6 = v1.z; g7 = v1.w;
            } else if (dc[k] > 0) {
                // cols j0+1..j0+8 ; j0+8 = next lane's v0.x (col 64 -> clamp 63 = v1.w)
                float e = __shfl_sync(0xffffffffu, v0.x, lane8 + 1, 8);
                if (lane8 == 7) e = v1.w;
                g0 = v0.y; g1 = v0.z; g2 = v0.w; g3 = v1.x;
                g4 = v1.y; g5 = v1.z; g6 = v1.w; g7 = e;
            } else {
                // cols j0-1..j0+6 ; j0-1 = prev lane's v1.w (col -1 -> clamp 0 = v0.x)
                float e = __shfl_sync(0xffffffffu, v1.w, lane8 - 1, 8);
                if (lane8 == 0) e = v0.x;
                g0 = e;    g1 = v0.x; g2 = v0.y; g3 = v0.z;
                g4 = v0.w; g5 = v1.x; g6 = v1.y; g7 = v1.z;
            }

            const float wk = w[k];
            m0 = fmaxf(m0, fabsf(wk - g0));
            m1 = fmaxf(m1, fabsf(wk - g1));
            m2 = fmaxf(m2, fabsf(wk - g2));
            m3 = fmaxf(m3, fabsf(wk - g3));
            m4 = fmaxf(m4, fabsf(wk - g4));
            m5 = fmaxf(m5, fabsf(wk - g5));
            m6 = fmaxf(m6, fabsf(wk - g6));
            m7 = fmaxf(m7, fabsf(wk - g7));
        }

        // Streaming stores: output is never re-read; keep L2 for the x gathers.
        __stcs(po + row * 16 + lane8 * 2,
               make_float4(m0 + bs, m1 + bs, m2 + bs, m3 + bs));
        __stcs(po + row * 16 + lane8 * 2 + 1,
               make_float4(m4 + bs, m5 + bs, m6 + bs, m7 + bs));
    }
}

extern "C" void kernel_launch(void* const* d_in, const int* in_sizes, int n_in,
                              void* d_out, int out_size) {
    const float* x       = (const float*)d_in[0];
    const float* weights = (const float*)d_in[1];
    const float* bias    = (const float*)d_in[2];
    const int*   conn    = (const int*)d_in[3];
    float*       out     = (float*)d_out;

    const int B = in_sizes[0] / (CIN * HW * HW);   // 32
    lp_conv_bt_kernel<<<B * COUT, 128>>>(x, weights, bias, conn, out);
}

// round 5
// speedup vs baseline: 1.5123x; 1.1699x over previous
#include <cuda_runtime.h>
#include <cuda_bf16.h>

// Lp_Conv2D_BT: out[b,o,i,j] = max_{k<4} | w[o,k] - x_pad[b, c_k, i+di_k-1, j+dj_k-1] | + bias[o]
// edge padding (clamp), stride 1.
// x:(32,64,64,64) f32; weights:(128,4) f32; bias:(128,1,1) f32; conn_idx:(128,4) i32.
// out:(32,128,64,64) f32.

namespace {
constexpr int HW   = 64;
constexpr int CIN  = 64;
constexpr int COUT = 128;
constexpr int CONN = 4;
}

__global__ __launch_bounds__(256) void lp_conv_bt_kernel(
    const float* __restrict__ x,
    const float* __restrict__ weights,
    const float* __restrict__ bias,
    const int*   __restrict__ conn_idx,
    float*       __restrict__ out)
{
    const int blk = blockIdx.x;          // blk = b*COUT + o
    const int o   = blk & (COUT - 1);
    const int b   = blk >> 7;
    const int t   = threadIdx.x;

    // Per-output-channel connection parameters (uniform across the block).
    const float* px[CONN];
    int dr[CONN], dc[CONN];
    float w[CONN];
#pragma unroll
    for (int k = 0; k < CONN; ++k) {
        const int idx = __ldg(conn_idx + o * CONN + k);   // [0, 576)
        const int c   = idx / 9;
        const int rem = idx - c * 9;
        const int di  = rem / 3;
        dr[k] = di - 1;                   // {-1,0,1}
        dc[k] = (rem - di * 3) - 1;       // {-1,0,1}, uniform per block
        px[k] = x + ((size_t)b * CIN + c) * (HW * HW);
        w[k]  = __ldg(weights + o * CONN + k);
    }
    const float bs = __ldg(bias + o);

    // Wavefront-optimal mapping: 16 lanes cover one row (contiguous float4 per
    // lane); a warp spans 2 adjacent rows -> each LDG.128 is 4x128B lines (min).
    const int lane16 = t & 15;
    const int r0     = t >> 4;           // 0..15
    float4* po = reinterpret_cast<float4*>(out + (size_t)blk * (HW * HW));

#pragma unroll
    for (int rb = 0; rb < 4; ++rb) {
        const int row = r0 + rb * 16;

        // Row clamp only at extreme row-blocks (dr in {-1,0,1}).
        const float4* p[CONN];
#pragma unroll
        for (int k = 0; k < CONN; ++k) {
            int rr = row + dr[k];
            if (rb == 0)      rr = max(rr, 0);
            else if (rb == 3) rr = min(rr, HW - 1);
            p[k] = reinterpret_cast<const float4*>(px[k] + rr * HW) + lane16;
        }

        // Issue the 4 independent LDG.128 before any dependent op.
        float4 v[CONN];
#pragma unroll
        for (int k = 0; k < CONN; ++k) v[k] = __ldg(p[k]);

        float m0 = 0.f, m1 = 0.f, m2 = 0.f, m3 = 0.f;   // |.| >= 0

#pragma unroll
        for (int k = 0; k < CONN; ++k) {
            const float4 vv = v[k];
            float g0, g1, g2, g3;
            if (dc[k] == 0) {
                g0 = vv.x; g1 = vv.y; g2 = vv.z; g3 = vv.w;
            } else if (dc[k] > 0) {
                // cols j0+1..j0+4 ; j0+4 = next lane's vv.x (col 64 -> clamp 63 = vv.w)
                float e = __shfl_down_sync(0xffffffffu, vv.x, 1, 16);
                if (lane16 == 15) e = vv.w;
                g0 = vv.y; g1 = vv.z; g2 = vv.w; g3 = e;
            } else {
                // cols j0-1..j0+2 ; j0-1 = prev lane's vv.w (col -1 -> clamp 0 = vv.x)
                float e = __shfl_up_sync(0xffffffffu, vv.w, 1, 16);
                if (lane16 == 0) e = vv.x;
                g0 = e; g1 = vv.x; g2 = vv.y; g3 = vv.z;
            }

            const float wk = w[k];
            m0 = fmaxf(m0, fabsf(wk - g0));
            m1 = fmaxf(m1, fabsf(wk - g1));
            m2 = fmaxf(m2, fabsf(wk - g2));
            m3 = fmaxf(m3, fabsf(wk - g3));
        }

        // Streaming store: contiguous float4 per lane (4 lines/warp, minimal).
        __stcs(po + row * 16 + lane16,
               make_float4(m0 + bs, m1 + bs, m2 + bs, m3 + bs));
    }
}

extern "C" void kernel_launch(void* const* d_in, const int* in_sizes, int n_in,
                              void* d_out, int out_size) {
    const float* x       = (const float*)d_in[0];
    const float* weights = (const float*)d_in[1];
    const float* bias    = (const float*)d_in[2];
    const int*   conn    = (const int*)d_in[3];
    float*       out     = (float*)d_out;

    const int B = in_sizes[0] / (CIN * HW * HW);   // 32
    lp_conv_bt_kernel<<<B * COUT, 256>>>(x, weights, bias, conn, out);
}